// round 12
// baseline (speedup 1.0000x reference)
#include <cuda_runtime.h>
#include <cstdint>
#include <math.h>

// Problem constants
#define S_LEN  128
#define BATCH  128
#define EDIM   64
#define HDIM   8
#define TDIM   12
#define NROWS  (S_LEN*BATCH)   // 16384
#define FULLM  0xffffffffu
#define NOPS   30
#define PROJ_ROWS 128
#define RECUR_BLKS 128
#define CNT_TARGET 1024u       // 128 batches * 8 lanes per step

// -------------------- device scratch (no allocations allowed) ---------------
__device__ float g_Zx[NROWS * 32];    // per-(s,b) input projection (+b_in+phi), 2 MB
__device__ float g_hs[NROWS * HDIM];  // hidden states hs[s][b][h], 512 KB
__device__ int   g_flag;              // 1 => sentence buffer is int32, 0 => int64
__device__ float g_phiq_c[8], g_phiq_s[8];
__device__ unsigned g_cnt[S_LEN];     // per-step completion counters

// ============================================================================
// numpy-legacy MT19937 — constexpr so the circuit STRUCTURE is compile-time.
// ============================================================================
namespace mtrng {
struct MT { uint32_t key[624]; int pos; };
constexpr void mt_seed(MT& st, uint32_t s) {
    for (int i = 0; i < 624; i++) { st.key[i] = s; s = 1812433253u * (s ^ (s >> 30)) + (uint32_t)i + 1u; }
    st.pos = 624;
}
constexpr void mt_gen(MT& st) {
    int i = 0; uint32_t y = 0;
    for (i = 0; i < 624 - 397; i++) {
        y = (st.key[i] & 0x80000000u) | (st.key[i + 1] & 0x7fffffffu);
        st.key[i] = st.key[i + 397] ^ (y >> 1) ^ ((y & 1u) ? 0x9908b0dfu : 0u);
    }
    for (; i < 623; i++) {
        y = (st.key[i] & 0x80000000u) | (st.key[i + 1] & 0x7fffffffu);
        st.key[i] = st.key[i - 227] ^ (y >> 1) ^ ((y & 1u) ? 0x9908b0dfu : 0u);
    }
    y = (st.key[623] & 0x80000000u) | (st.key[0] & 0x7fffffffu);
    st.key[623] = st.key[396] ^ (y >> 1) ^ ((y & 1u) ? 0x9908b0dfu : 0u);
    st.pos = 0;
}
constexpr uint32_t mt_next(MT& st) {
    if (st.pos == 624) mt_gen(st);
    uint32_t y = st.key[st.pos++];
    y ^= y >> 11; y ^= (y << 7) & 0x9d2c5680u; y ^= (y << 15) & 0xefc60000u; y ^= y >> 18;
    return y;
}
constexpr int mt_randint(MT& st, uint32_t n) {
    uint32_t rng = n - 1u;
    uint32_t mask = rng;
    mask |= mask >> 1; mask |= mask >> 2; mask |= mask >> 4; mask |= mask >> 8; mask |= mask >> 16;
    uint32_t v = 0;
    do { v = mt_next(st) & mask; } while (v > rng);
    return (int)v;
}
constexpr double mt_double(MT& st) {
    uint32_t a = mt_next(st) >> 5, b = mt_next(st) >> 6;
    return ((double)a * 67108864.0 + (double)b) / 9007199254740992.0;
}
} // namespace mtrng

// Compile-time circuit structure
struct COps { int type[NOPS]; int pa[NOPS]; int pb[NOPS]; };
constexpr COps make_cops() {
    COps P{};
    mtrng::MT st{}; mtrng::mt_seed(st, 1234u);
    for (int i = 0; i < NOPS; i++) {
        int kind = mtrng::mt_randint(st, 4);
        if (kind == 3) {
            int c = mtrng::mt_randint(st, 8);
            int t = mtrng::mt_randint(st, 7);
            if (t >= c) t += 1;
            P.type[i] = 3; P.pa[i] = c; P.pb[i] = t;
        } else {
            int g = kind % 3;
            int w = mtrng::mt_randint(st, 8);
            (void)mtrng::mt_double(st);   // consume the angle draws
            P.type[i] = g; P.pa[i] = w; P.pb[i] = -1;
        }
    }
    return P;
}
constexpr COps COPS = make_cops();

// Runtime angle values (same MT walk; structure must match COPS)
struct Angles { float c[NOPS]; float s[NOPS]; };
static void build_angles(Angles& A) {
    mtrng::MT st; mtrng::mt_seed(st, 1234u);
    for (int i = 0; i < NOPS; i++) {
        int kind = mtrng::mt_randint(st, 4);
        if (kind == 3) {
            (void)mtrng::mt_randint(st, 8);
            (void)mtrng::mt_randint(st, 7);
            A.c[i] = 0.f; A.s[i] = 0.f;
        } else {
            (void)mtrng::mt_randint(st, 8);
            double ang = mtrng::mt_double(st) * (2.0 * M_PI);
            float th = (float)ang;            // reference casts to float32
            double half = (double)(th * 0.5f);
            A.c[i] = (float)cos(half); A.s[i] = (float)sin(half);
        }
    }
}

// ---------------- acquire/release helpers ----------------
__device__ __forceinline__ unsigned ld_acquire(const unsigned* p) {
    unsigned v;
    asm volatile("ld.acquire.gpu.global.u32 %0, [%1];" : "=r"(v) : "l"(p) : "memory");
    return v;
}
__device__ __forceinline__ void red_release_add(unsigned* p, unsigned v) {
    asm volatile("red.release.gpu.global.add.u32 [%0], %1;" :: "l"(p), "r"(v) : "memory");
}
__device__ __forceinline__ float fast_tanh(float x) {
    float r; asm("tanh.approx.f32 %0, %1;" : "=f"(r) : "f"(x)); return r;
}

// ============================================================================
// Kernel A: detect sentence dtype + precompute phiq cos/sin + zero counters
// ============================================================================
__global__ void k_detect(const int4* __restrict__ sent4, const float* __restrict__ phiq) {
    __shared__ int any;
    if (threadIdx.x == 0) any = 0;
    __syncthreads();
    int loc = 0;
    for (int i = threadIdx.x; i < 4096; i += blockDim.x) {
        int4 v = sent4[i];
        loc |= v.y | v.w;
    }
    if (loc) atomicOr(&any, 1);
    __syncthreads();
    if (threadIdx.x == 0) g_flag = any ? 1 : 0;
    if (threadIdx.x < 8) {
        float c, s;
        __sincosf(0.5f * phiq[threadIdx.x], &s, &c);
        g_phiq_c[threadIdx.x] = c;
        g_phiq_s[threadIdx.x] = s;
    }
    if (threadIdx.x < S_LEN) g_cnt[threadIdx.x] = 0u;
}

// ============================================================================
// Kernel B: embed-gather + input projection as smem-tiled GEMM.
// ============================================================================
__global__ void __launch_bounds__(256) k_project(const float* __restrict__ emb,
                                                 const float* __restrict__ Win,
                                                 const float* __restrict__ b_in,
                                                 const float* __restrict__ phi,
                                                 const int*   __restrict__ sent32) {
    __shared__ __align__(16) float sX[PROJ_ROWS][65];
    __shared__ __align__(16) float sW[64][36];
    __shared__ __align__(16) float sB[32];

    int tid  = threadIdx.x;
    int lane = tid & 31;
    int wid  = tid >> 5;
    int rowbase = blockIdx.x * PROJ_ROWS;
    int flag = g_flag;

#pragma unroll
    for (int j = 0; j < 8; j++) {
        int i = tid + j * 256;
        int o = i & 31, k = i >> 5;
        sW[k][o] = Win[o * 72 + k];
    }
    if (tid < 32) sB[tid] = b_in[tid] + phi[tid];

    for (int r = wid; r < PROJ_ROWS; r += 8) {
        int rr = rowbase + r;
        int tok = sent32[flag ? rr : 2 * rr];
        const float* xr = emb + (long)tok * EDIM;
        sX[r][lane]      = xr[lane];
        sX[r][lane + 32] = xr[lane + 32];
    }
    __syncthreads();

    int c0 = (tid & 7) * 4;
    int r0 = (tid >> 3) * 4;
    float acc[4][4];
    {
        float4 bv = *reinterpret_cast<const float4*>(&sB[c0]);
#pragma unroll
        for (int i = 0; i < 4; i++) {
            acc[i][0] = bv.x; acc[i][1] = bv.y; acc[i][2] = bv.z; acc[i][3] = bv.w;
        }
    }

#pragma unroll 4
    for (int k = 0; k < 64; k++) {
        float4 w = *reinterpret_cast<const float4*>(&sW[k][c0]);
        float x0 = sX[r0][k];
        float x1 = sX[r0 + 1][k];
        float x2 = sX[r0 + 2][k];
        float x3 = sX[r0 + 3][k];
        acc[0][0] = fmaf(x0, w.x, acc[0][0]); acc[0][1] = fmaf(x0, w.y, acc[0][1]);
        acc[0][2] = fmaf(x0, w.z, acc[0][2]); acc[0][3] = fmaf(x0, w.w, acc[0][3]);
        acc[1][0] = fmaf(x1, w.x, acc[1][0]); acc[1][1] = fmaf(x1, w.y, acc[1][1]);
        acc[1][2] = fmaf(x1, w.z, acc[1][2]); acc[1][3] = fmaf(x1, w.w, acc[1][3]);
        acc[2][0] = fmaf(x2, w.x, acc[2][0]); acc[2][1] = fmaf(x2, w.y, acc[2][1]);
        acc[2][2] = fmaf(x2, w.z, acc[2][2]); acc[2][3] = fmaf(x2, w.w, acc[2][3]);
        acc[3][0] = fmaf(x3, w.x, acc[3][0]); acc[3][1] = fmaf(x3, w.y, acc[3][1]);
        acc[3][2] = fmaf(x3, w.z, acc[3][2]); acc[3][3] = fmaf(x3, w.w, acc[3][3]);
    }

#pragma unroll
    for (int i = 0; i < 4; i++) {
        float4 v = make_float4(acc[i][0], acc[i][1], acc[i][2], acc[i][3]);
        *reinterpret_cast<float4*>(&g_Zx[(rowbase + r0 + i) * 32 + c0]) = v;
    }
}

// ============================================================================
// Head circuit helpers — compile-time-specialized.
// 256 amps: lane holds amps m = lane*8 + k. wire w <-> bit (7-w).
// ============================================================================
template<int BB, bool RX>
__device__ __forceinline__ void rot_lane_t(float* ar, float* ai, float c, float s, int lane) {
    constexpr int delta = 1 << (BB - 3);
    float sgn = ((lane >> (BB - 3)) & 1) ? s : -s;   // for RY
#pragma unroll
    for (int k = 0; k < 8; k++) {
        float pr = __shfl_xor_sync(FULLM, ar[k], delta);
        float pi = __shfl_xor_sync(FULLM, ai[k], delta);
        if (RX) {
            float nr = fmaf(s, pi, c * ar[k]);
            float ni = fmaf(-s, pr, c * ai[k]);
            ar[k] = nr; ai[k] = ni;
        } else {
            ar[k] = fmaf(sgn, pr, c * ar[k]);
            ai[k] = fmaf(sgn, pi, c * ai[k]);
        }
    }
}

template<int M, bool RX>
__device__ __forceinline__ void rot_intra_tt(float* ar, float* ai, float c, float s) {
#pragma unroll
    for (int k = 0; k < 8; k++) {
        if (!(k & M)) {
            const int k1 = k | M;
            float a0r = ar[k], a0i = ai[k], a1r = ar[k1], a1i = ai[k1];
            if (RX) {
                ar[k]  = fmaf(s, a1i, c * a0r);  ai[k]  = fmaf(-s, a1r, c * a0i);
                ar[k1] = fmaf(s, a0i, c * a1r);  ai[k1] = fmaf(-s, a0r, c * a1i);
            } else {
                ar[k]  = fmaf(-s, a1r, c * a0r); ai[k]  = fmaf(-s, a1i, c * a0i);
                ar[k1] = fmaf( s, a0r, c * a1r); ai[k1] = fmaf( s, a0i, c * a1i);
            }
        }
    }
}

template<int BB>
__device__ __forceinline__ void rz_t(float* ar, float* ai, float c, float s, int lane) {
    if (BB >= 3) {
        float sg = ((lane >> (BB - 3)) & 1) ? -s : s;
#pragma unroll
        for (int k = 0; k < 8; k++) {
            float nr = fmaf(sg, ai[k], c * ar[k]);
            float ni = fmaf(-sg, ar[k], c * ai[k]);
            ar[k] = nr; ai[k] = ni;
        }
    } else {
#pragma unroll
        for (int k = 0; k < 8; k++) {
            float sg = ((k >> BB) & 1) ? -s : s;
            float nr = fmaf(sg, ai[k], c * ar[k]);
            float ni = fmaf(-sg, ar[k], c * ai[k]);
            ar[k] = nr; ai[k] = ni;
        }
    }
}

template<int BC, int BT>
__device__ __forceinline__ void cnot_t(float* ar, float* ai, int lane) {
    if (BC >= 3 && BT >= 3) {
        constexpr int delta = (BT >= 3) ? (1 << (BT - 3)) : 1;
        int ctrl = (lane >> (BC - 3)) & 1;
#pragma unroll
        for (int k = 0; k < 8; k++) {
            float pr = __shfl_xor_sync(FULLM, ar[k], delta);
            float pi = __shfl_xor_sync(FULLM, ai[k], delta);
            if (ctrl) { ar[k] = pr; ai[k] = pi; }
        }
    } else if (BC >= 3) {
        constexpr int M = (BT < 3) ? (1 << BT) : 1;
        bool ctrl = ((lane >> (BC - 3)) & 1) != 0;
#pragma unroll
        for (int k = 0; k < 8; k++) if (!(k & M)) {
            const int k1 = k | M;
            float t0r = ctrl ? ar[k1] : ar[k];
            float t1r = ctrl ? ar[k]  : ar[k1];
            float t0i = ctrl ? ai[k1] : ai[k];
            float t1i = ctrl ? ai[k]  : ai[k1];
            ar[k] = t0r; ar[k1] = t1r; ai[k] = t0i; ai[k1] = t1i;
        }
    } else if (BT >= 3) {
        constexpr int delta = (BT >= 3) ? (1 << (BT - 3)) : 1;
        constexpr int MC = (BC < 3) ? (1 << BC) : 1;
#pragma unroll
        for (int k = 0; k < 8; k++) if (k & MC) {
            ar[k] = __shfl_xor_sync(FULLM, ar[k], delta);
            ai[k] = __shfl_xor_sync(FULLM, ai[k], delta);
        }
    } else {
        constexpr int MC = (BC < 3) ? (1 << BC) : 1;
        constexpr int M  = (BT < 3) ? (1 << BT) : 1;
#pragma unroll
        for (int k = 0; k < 8; k++) if ((k & MC) && !(k & M)) {
            const int k1 = k | M;
            float t = ar[k]; ar[k] = ar[k1]; ar[k1] = t;
            t = ai[k]; ai[k] = ai[k1]; ai[k1] = t;
        }
    }
}

template<int I>
__device__ __forceinline__ void apply_ops(float* ar, float* ai,
                                          const float* Pc, const float* Ps, int lane) {
    if constexpr (I < NOPS) {
        constexpr int ty = COPS.type[I];
        if constexpr (ty == 3) {
            cnot_t<7 - COPS.pa[I], 7 - COPS.pb[I]>(ar, ai, lane);
        } else {
            constexpr int bb = 7 - COPS.pa[I];
            const float c = Pc[I], s = Ps[I];
            if constexpr (ty == 2)      rz_t<bb>(ar, ai, c, s, lane);
            else if constexpr (bb >= 3) rot_lane_t<bb, ty == 0>(ar, ai, c, s, lane);
            else                        rot_intra_tt<(1 << bb), ty == 0>(ar, ai, c, s);
        }
        apply_ops<I + 1>(ar, ai, Pc, Ps, lane);
    }
}

template<int W>
__device__ __forceinline__ void apply_phiq(float* ar, float* ai, int lane) {
    if constexpr (W < 8) {
        float c = g_phiq_c[W];
        float s = g_phiq_s[W];
        constexpr int BB = 7 - W;
        if constexpr (BB >= 3) rot_lane_t<BB, true>(ar, ai, c, s, lane);
        else                   rot_intra_tt<(1 << BB), true>(ar, ai, c, s);
        apply_phiq<W + 1>(ar, ai, lane);
    }
}

// ============================================================================
// FUSED kernel: blocks 0..127 = recurrence (warp 0 only); blocks 128.. = head.
// Recur signals per-step completion via release-RED on g_cnt[s]; head warps
// acquire-spin until their step is ready, then run the quantum head.
// ============================================================================
__global__ void __launch_bounds__(256) k_fused(const float* __restrict__ Win,
                                               const float* __restrict__ Wout,
                                               const float* __restrict__ b_out,
                                               const float* __restrict__ Whead,
                                               const float* __restrict__ b_head,
                                               float* __restrict__ out,
                                               Angles A) {
    int bid = blockIdx.x;
    int tid = threadIdx.x;
    int lane = tid & 31;
    int wid  = tid >> 5;

    if (bid < RECUR_BLKS) {
        // ---------------- recurrence role: warp 0 only ----------------
        if (wid != 0) return;
        __shared__ __align__(16) float sp[32];
        __shared__ __align__(16) float sact[32];
        __shared__ __align__(16) float sh[8];

        int b = bid;
        int g = lane >> 3;
        int q = lane & 7;
        int base = lane & 24;

        float Wh[8];
#pragma unroll
        for (int j = 0; j < 8; j++) Wh[j] = Win[lane * 72 + 64 + j];
        float Wo[8];
#pragma unroll
        for (int j = 0; j < 8; j++) Wo[j] = Wout[g * 64 + q * 8 + j];
        float bo = b_out[lane];

        float aAB = (g == 2) ? 1.f : 0.5f;
        float aC  = (g == 2) ? 0.f : 0.5f;

        float h[8];
#pragma unroll
        for (int j = 0; j < 8; j++) h[j] = 0.f;
        float cst = 0.f;

        const int BSTR = BATCH * 32;
        const float* Zp = g_Zx + b * 32 + lane;
        float zA = Zp[0];
        float zB = Zp[BSTR];

#pragma unroll 2
        for (int s = 0; s < S_LEN; s++) {
            float zC = (s + 2 < S_LEN) ? Zp[(s + 2) * BSTR] : 0.f;

            float za = zA, zb = 0.f;
#pragma unroll
            for (int j = 0; j < 8; j += 2) {
                za = fmaf(Wh[j],     h[j],     za);
                zb = fmaf(Wh[j + 1], h[j + 1], zb);
            }
            float p = __cosf(za + zb);

            sp[lane] = p;
            __syncwarp();
            float4 pa = *reinterpret_cast<const float4*>(sp + base);
            float4 pb = *reinterpret_cast<const float4*>(sp + base + 4);

            float t01 = pa.x * pa.y, t23 = pa.z * pa.w;
            float t45 = pb.x * pb.y, t67 = pb.z * pb.w;
            float q03 = t01 * t23;
            float P0 = pa.x;
            float P1 = t01;
            float P2 = t01 * pa.z;
            float P3 = q03;
            float P4 = q03 * pb.x;
            float P5 = q03 * t45;
            float P6 = P5 * pb.z;
            float P7 = q03 * (t45 * t67);

            float prA = fmaf(Wo[0], P0, bo);
            float prB = Wo[1] * P1;
            prA = fmaf(Wo[2], P2, prA);
            prB = fmaf(Wo[3], P3, prB);
            prA = fmaf(Wo[4], P4, prA);
            prB = fmaf(Wo[5], P5, prB);
            prA = fmaf(Wo[6], P6, prA);
            prB = fmaf(Wo[7], P7, prB);
            float pre = prA + prB;

            float act = fmaf(aAB, fast_tanh(aAB * pre), aC);

            sact[lane] = act;
            __syncwarp();
            float fv = sact[q];
            float iv = sact[8 + q];
            float gv = sact[16 + q];
            float ov = sact[24 + q];

            cst = fmaf(fv, cst, iv * gv);
            float hval = ov * fast_tanh(cst);

            if (lane < 8) {
                sh[lane] = hval;
                g_hs[(s * BATCH + b) * HDIM + lane] = hval;
                // release: orders this lane's g_hs store before the count bump
                red_release_add(&g_cnt[s], 1u);
            }
            __syncwarp();
            float4 h0 = *reinterpret_cast<const float4*>(sh);
            float4 h1 = *reinterpret_cast<const float4*>(sh + 4);
            h[0] = h0.x; h[1] = h0.y; h[2] = h0.z; h[3] = h0.w;
            h[4] = h1.x; h[5] = h1.y; h[6] = h1.z; h[7] = h1.w;

            zA = zB; zB = zC;
        }
        return;
    }

    // ---------------- head role ----------------
    int r = (bid - RECUR_BLKS) * 8 + wid;   // output row
    int sp_ = r >> 7;       // s'
    int bp  = r & 127;      // b'  -> needs recurrence step s = bp
    int hoff = ((bp << 7) + sp_) * HDIM;

    // wait until all 128 batches have published step bp (acquire per lane)
    while (ld_acquire(&g_cnt[bp]) < CNT_TARGET) __nanosleep(256);
    __syncwarp();

    // ---- encode: product state from RY angles ----
    float ce = 1.f, se = 0.f;
    if (lane < 8) {
        float th = 0.5f * g_hs[hoff + lane];
        __sincosf(th, &se, &ce);
    }
    float Fl = 1.f;
#pragma unroll
    for (int w = 0; w < 5; w++) {
        float cw = __shfl_sync(FULLM, ce, w);
        float sw = __shfl_sync(FULLM, se, w);
        Fl *= ((lane >> (4 - w)) & 1) ? sw : cw;
    }
    float c5 = __shfl_sync(FULLM, ce, 5), s5v = __shfl_sync(FULLM, se, 5);
    float c6 = __shfl_sync(FULLM, ce, 6), s6v = __shfl_sync(FULLM, se, 6);
    float c7 = __shfl_sync(FULLM, ce, 7), s7v = __shfl_sync(FULLM, se, 7);
    float ar[8], ai[8];
#pragma unroll
    for (int k = 0; k < 8; k++) {
        float f = ((k & 4) ? s5v : c5) * ((k & 2) ? s6v : c6) * ((k & 1) ? s7v : c7);
        ar[k] = Fl * f; ai[k] = 0.f;
    }

    apply_ops<0>(ar, ai, A.c, A.s, lane);
    apply_phiq<0>(ar, ai, lane);

    // ---- measure <Z_w> ----
    float p[8];
#pragma unroll
    for (int k = 0; k < 8; k++) p[k] = fmaf(ar[k], ar[k], ai[k] * ai[k]);
    float tot = 0.f, sA = 0.f, sB = 0.f, sC = 0.f;
#pragma unroll
    for (int k = 0; k < 8; k++) {
        tot += p[k];
        sA += (k & 4) ? -p[k] : p[k];
        sB += (k & 2) ? -p[k] : p[k];
        sC += (k & 1) ? -p[k] : p[k];
    }
    float x = tot;
#pragma unroll
    for (int d = 16; d >= 1; d >>= 1) {
        float o = __shfl_xor_sync(FULLM, x, d);
        x = (lane & d) ? (o - x) : (x + o);
    }
    float z[8];
    z[0] = __shfl_sync(FULLM, x, 16);
    z[1] = __shfl_sync(FULLM, x, 8);
    z[2] = __shfl_sync(FULLM, x, 4);
    z[3] = __shfl_sync(FULLM, x, 2);
    z[4] = __shfl_sync(FULLM, x, 1);
#pragma unroll
    for (int d = 16; d >= 1; d >>= 1) {
        sA += __shfl_xor_sync(FULLM, sA, d);
        sB += __shfl_xor_sync(FULLM, sB, d);
        sC += __shfl_xor_sync(FULLM, sC, d);
    }
    z[5] = sA; z[6] = sB; z[7] = sC;

    // ---- logits + log_softmax over T=12 ----
    float lg = 0.f;
    if (lane < TDIM) {
        lg = b_head[lane];
#pragma unroll
        for (int k = 0; k < 8; k++) lg = fmaf(z[k], Whead[lane * 8 + k], lg);
    }
    float mv = (lane < TDIM) ? lg : -3.0e38f;
#pragma unroll
    for (int d = 16; d >= 1; d >>= 1) mv = fmaxf(mv, __shfl_xor_sync(FULLM, mv, d));
    float ev = (lane < TDIM) ? __expf(lg - mv) : 0.f;
#pragma unroll
    for (int d = 16; d >= 1; d >>= 1) ev += __shfl_xor_sync(FULLM, ev, d);
    if (lane < TDIM) out[r * TDIM + lane] = lg - mv - __logf(ev);
}

// ============================================================================
// Launch
// ============================================================================
extern "C" void kernel_launch(void* const* d_in, const int* in_sizes, int n_in,
                              void* d_out, int out_size) {
    (void)in_sizes; (void)n_in; (void)out_size;
    const float* emb    = (const float*)d_in[0];
    const float* Win    = (const float*)d_in[1];
    const float* b_in   = (const float*)d_in[2];
    const float* phi    = (const float*)d_in[3];
    const float* Wout   = (const float*)d_in[4];
    const float* b_out  = (const float*)d_in[5];
    const float* phiq   = (const float*)d_in[6];
    const float* Whead  = (const float*)d_in[7];
    const float* b_head = (const float*)d_in[8];
    const int*   sent32 = (const int*)d_in[9];
    float* out = (float*)d_out;

    Angles A;
    build_angles(A);   // deterministic; recomputed every call (cheap)

    k_detect<<<1, 256>>>((const int4*)sent32, phiq);
    k_project<<<NROWS / PROJ_ROWS, 256>>>(emb, Win, b_in, phi, sent32);
    k_fused<<<RECUR_BLKS + NROWS / 8, 256>>>(Win, Wout, b_out, Whead, b_head, out, A);
}

// round 13
// speedup vs baseline: 3.5731x; 3.5731x over previous
#include <cuda_runtime.h>
#include <cstdint>
#include <math.h>

// Problem constants
#define S_LEN  128
#define BATCH  128
#define EDIM   64
#define HDIM   8
#define TDIM   12
#define NROWS  (S_LEN*BATCH)   // 16384
#define FULLM  0xffffffffu
#define NOPS   30
#define PROJ_ROWS 128
#define RECUR_BLKS 128
#define CNT_STRIDE 32          // 128-byte pad: one L2 line per step counter
#define CNT_TARGET 128u        // one release per batch CTA per step

// -------------------- device scratch (no allocations allowed) ---------------
__device__ float g_Zx[NROWS * 32];    // per-(s,b) input projection (+b_in+phi), 2 MB
__device__ float g_hs[NROWS * HDIM];  // hidden states hs[s][b][h], 512 KB
__device__ int   g_flag;              // 1 => sentence buffer is int32, 0 => int64
__device__ float g_phiq_c[8], g_phiq_s[8];
__device__ unsigned g_cnt[S_LEN * CNT_STRIDE];   // padded per-step counters

// ============================================================================
// numpy-legacy MT19937 — constexpr so the circuit STRUCTURE is compile-time.
// ============================================================================
namespace mtrng {
struct MT { uint32_t key[624]; int pos; };
constexpr void mt_seed(MT& st, uint32_t s) {
    for (int i = 0; i < 624; i++) { st.key[i] = s; s = 1812433253u * (s ^ (s >> 30)) + (uint32_t)i + 1u; }
    st.pos = 624;
}
constexpr void mt_gen(MT& st) {
    int i = 0; uint32_t y = 0;
    for (i = 0; i < 624 - 397; i++) {
        y = (st.key[i] & 0x80000000u) | (st.key[i + 1] & 0x7fffffffu);
        st.key[i] = st.key[i + 397] ^ (y >> 1) ^ ((y & 1u) ? 0x9908b0dfu : 0u);
    }
    for (; i < 623; i++) {
        y = (st.key[i] & 0x80000000u) | (st.key[i + 1] & 0x7fffffffu);
        st.key[i] = st.key[i - 227] ^ (y >> 1) ^ ((y & 1u) ? 0x9908b0dfu : 0u);
    }
    y = (st.key[623] & 0x80000000u) | (st.key[0] & 0x7fffffffu);
    st.key[623] = st.key[396] ^ (y >> 1) ^ ((y & 1u) ? 0x9908b0dfu : 0u);
    st.pos = 0;
}
constexpr uint32_t mt_next(MT& st) {
    if (st.pos == 624) mt_gen(st);
    uint32_t y = st.key[st.pos++];
    y ^= y >> 11; y ^= (y << 7) & 0x9d2c5680u; y ^= (y << 15) & 0xefc60000u; y ^= y >> 18;
    return y;
}
constexpr int mt_randint(MT& st, uint32_t n) {
    uint32_t rng = n - 1u;
    uint32_t mask = rng;
    mask |= mask >> 1; mask |= mask >> 2; mask |= mask >> 4; mask |= mask >> 8; mask |= mask >> 16;
    uint32_t v = 0;
    do { v = mt_next(st) & mask; } while (v > rng);
    return (int)v;
}
constexpr double mt_double(MT& st) {
    uint32_t a = mt_next(st) >> 5, b = mt_next(st) >> 6;
    return ((double)a * 67108864.0 + (double)b) / 9007199254740992.0;
}
} // namespace mtrng

// Compile-time circuit structure
struct COps { int type[NOPS]; int pa[NOPS]; int pb[NOPS]; };
constexpr COps make_cops() {
    COps P{};
    mtrng::MT st{}; mtrng::mt_seed(st, 1234u);
    for (int i = 0; i < NOPS; i++) {
        int kind = mtrng::mt_randint(st, 4);
        if (kind == 3) {
            int c = mtrng::mt_randint(st, 8);
            int t = mtrng::mt_randint(st, 7);
            if (t >= c) t += 1;
            P.type[i] = 3; P.pa[i] = c; P.pb[i] = t;
        } else {
            int g = kind % 3;
            int w = mtrng::mt_randint(st, 8);
            (void)mtrng::mt_double(st);   // consume the angle draws
            P.type[i] = g; P.pa[i] = w; P.pb[i] = -1;
        }
    }
    return P;
}
constexpr COps COPS = make_cops();

// Runtime angle values (same MT walk; structure must match COPS)
struct Angles { float c[NOPS]; float s[NOPS]; };
static void build_angles(Angles& A) {
    mtrng::MT st; mtrng::mt_seed(st, 1234u);
    for (int i = 0; i < NOPS; i++) {
        int kind = mtrng::mt_randint(st, 4);
        if (kind == 3) {
            (void)mtrng::mt_randint(st, 8);
            (void)mtrng::mt_randint(st, 7);
            A.c[i] = 0.f; A.s[i] = 0.f;
        } else {
            (void)mtrng::mt_randint(st, 8);
            double ang = mtrng::mt_double(st) * (2.0 * M_PI);
            float th = (float)ang;            // reference casts to float32
            double half = (double)(th * 0.5f);
            A.c[i] = (float)cos(half); A.s[i] = (float)sin(half);
        }
    }
}

// ---------------- acquire/release helpers ----------------
__device__ __forceinline__ unsigned ld_acquire(const unsigned* p) {
    unsigned v;
    asm volatile("ld.acquire.gpu.global.u32 %0, [%1];" : "=r"(v) : "l"(p) : "memory");
    return v;
}
__device__ __forceinline__ void red_release_add(unsigned* p, unsigned v) {
    asm volatile("red.release.gpu.global.add.u32 [%0], %1;" :: "l"(p), "r"(v) : "memory");
}
__device__ __forceinline__ float fast_tanh(float x) {
    float r; asm("tanh.approx.f32 %0, %1;" : "=f"(r) : "f"(x)); return r;
}

// ============================================================================
// Kernel A: detect dtype + phiq sincos + zero padded counters (1024 threads)
// ============================================================================
__global__ void __launch_bounds__(1024) k_detect(const int4* __restrict__ sent4,
                                                 const float* __restrict__ phiq) {
    __shared__ int any;
    int tid = threadIdx.x;
    if (tid == 0) any = 0;
    __syncthreads();
    int loc = 0;
#pragma unroll
    for (int j = 0; j < 4; j++) {
        int4 v = sent4[tid + j * 1024];
        loc |= v.y | v.w;
    }
    if (loc) atomicOr(&any, 1);
    // zero padded counters (before syncthreads; independent)
    for (int i = tid; i < S_LEN * CNT_STRIDE; i += 1024) g_cnt[i] = 0u;
    __syncthreads();
    if (tid == 0) g_flag = any ? 1 : 0;
    if (tid < 8) {
        float c, s;
        __sincosf(0.5f * phiq[tid], &s, &c);
        g_phiq_c[tid] = c;
        g_phiq_s[tid] = s;
    }
}

// ============================================================================
// Kernel B: embed-gather + input projection as smem-tiled GEMM.
// ============================================================================
__global__ void __launch_bounds__(256) k_project(const float* __restrict__ emb,
                                                 const float* __restrict__ Win,
                                                 const float* __restrict__ b_in,
                                                 const float* __restrict__ phi,
                                                 const int*   __restrict__ sent32) {
    __shared__ __align__(16) float sX[PROJ_ROWS][65];
    __shared__ __align__(16) float sW[64][36];
    __shared__ __align__(16) float sB[32];

    int tid  = threadIdx.x;
    int lane = tid & 31;
    int wid  = tid >> 5;
    int rowbase = blockIdx.x * PROJ_ROWS;
    int flag = g_flag;

#pragma unroll
    for (int j = 0; j < 8; j++) {
        int i = tid + j * 256;
        int o = i & 31, k = i >> 5;
        sW[k][o] = Win[o * 72 + k];
    }
    if (tid < 32) sB[tid] = b_in[tid] + phi[tid];

    for (int r = wid; r < PROJ_ROWS; r += 8) {
        int rr = rowbase + r;
        int tok = sent32[flag ? rr : 2 * rr];
        const float* xr = emb + (long)tok * EDIM;
        sX[r][lane]      = xr[lane];
        sX[r][lane + 32] = xr[lane + 32];
    }
    __syncthreads();

    int c0 = (tid & 7) * 4;
    int r0 = (tid >> 3) * 4;
    float acc[4][4];
    {
        float4 bv = *reinterpret_cast<const float4*>(&sB[c0]);
#pragma unroll
        for (int i = 0; i < 4; i++) {
            acc[i][0] = bv.x; acc[i][1] = bv.y; acc[i][2] = bv.z; acc[i][3] = bv.w;
        }
    }

#pragma unroll 4
    for (int k = 0; k < 64; k++) {
        float4 w = *reinterpret_cast<const float4*>(&sW[k][c0]);
        float x0 = sX[r0][k];
        float x1 = sX[r0 + 1][k];
        float x2 = sX[r0 + 2][k];
        float x3 = sX[r0 + 3][k];
        acc[0][0] = fmaf(x0, w.x, acc[0][0]); acc[0][1] = fmaf(x0, w.y, acc[0][1]);
        acc[0][2] = fmaf(x0, w.z, acc[0][2]); acc[0][3] = fmaf(x0, w.w, acc[0][3]);
        acc[1][0] = fmaf(x1, w.x, acc[1][0]); acc[1][1] = fmaf(x1, w.y, acc[1][1]);
        acc[1][2] = fmaf(x1, w.z, acc[1][2]); acc[1][3] = fmaf(x1, w.w, acc[1][3]);
        acc[2][0] = fmaf(x2, w.x, acc[2][0]); acc[2][1] = fmaf(x2, w.y, acc[2][1]);
        acc[2][2] = fmaf(x2, w.z, acc[2][2]); acc[2][3] = fmaf(x2, w.w, acc[2][3]);
        acc[3][0] = fmaf(x3, w.x, acc[3][0]); acc[3][1] = fmaf(x3, w.y, acc[3][1]);
        acc[3][2] = fmaf(x3, w.z, acc[3][2]); acc[3][3] = fmaf(x3, w.w, acc[3][3]);
    }

#pragma unroll
    for (int i = 0; i < 4; i++) {
        float4 v = make_float4(acc[i][0], acc[i][1], acc[i][2], acc[i][3]);
        *reinterpret_cast<float4*>(&g_Zx[(rowbase + r0 + i) * 32 + c0]) = v;
    }
}

// ============================================================================
// Head circuit helpers — compile-time-specialized.
// ============================================================================
template<int BB, bool RX>
__device__ __forceinline__ void rot_lane_t(float* ar, float* ai, float c, float s, int lane) {
    constexpr int delta = 1 << (BB - 3);
    float sgn = ((lane >> (BB - 3)) & 1) ? s : -s;   // for RY
#pragma unroll
    for (int k = 0; k < 8; k++) {
        float pr = __shfl_xor_sync(FULLM, ar[k], delta);
        float pi = __shfl_xor_sync(FULLM, ai[k], delta);
        if (RX) {
            float nr = fmaf(s, pi, c * ar[k]);
            float ni = fmaf(-s, pr, c * ai[k]);
            ar[k] = nr; ai[k] = ni;
        } else {
            ar[k] = fmaf(sgn, pr, c * ar[k]);
            ai[k] = fmaf(sgn, pi, c * ai[k]);
        }
    }
}

template<int M, bool RX>
__device__ __forceinline__ void rot_intra_tt(float* ar, float* ai, float c, float s) {
#pragma unroll
    for (int k = 0; k < 8; k++) {
        if (!(k & M)) {
            const int k1 = k | M;
            float a0r = ar[k], a0i = ai[k], a1r = ar[k1], a1i = ai[k1];
            if (RX) {
                ar[k]  = fmaf(s, a1i, c * a0r);  ai[k]  = fmaf(-s, a1r, c * a0i);
                ar[k1] = fmaf(s, a0i, c * a1r);  ai[k1] = fmaf(-s, a0r, c * a1i);
            } else {
                ar[k]  = fmaf(-s, a1r, c * a0r); ai[k]  = fmaf(-s, a1i, c * a0i);
                ar[k1] = fmaf( s, a0r, c * a1r); ai[k1] = fmaf( s, a0i, c * a1i);
            }
        }
    }
}

template<int BB>
__device__ __forceinline__ void rz_t(float* ar, float* ai, float c, float s, int lane) {
    if (BB >= 3) {
        float sg = ((lane >> (BB - 3)) & 1) ? -s : s;
#pragma unroll
        for (int k = 0; k < 8; k++) {
            float nr = fmaf(sg, ai[k], c * ar[k]);
            float ni = fmaf(-sg, ar[k], c * ai[k]);
            ar[k] = nr; ai[k] = ni;
        }
    } else {
#pragma unroll
        for (int k = 0; k < 8; k++) {
            float sg = ((k >> BB) & 1) ? -s : s;
            float nr = fmaf(sg, ai[k], c * ar[k]);
            float ni = fmaf(-sg, ar[k], c * ai[k]);
            ar[k] = nr; ai[k] = ni;
        }
    }
}

template<int BC, int BT>
__device__ __forceinline__ void cnot_t(float* ar, float* ai, int lane) {
    if (BC >= 3 && BT >= 3) {
        constexpr int delta = (BT >= 3) ? (1 << (BT - 3)) : 1;
        int ctrl = (lane >> (BC - 3)) & 1;
#pragma unroll
        for (int k = 0; k < 8; k++) {
            float pr = __shfl_xor_sync(FULLM, ar[k], delta);
            float pi = __shfl_xor_sync(FULLM, ai[k], delta);
            if (ctrl) { ar[k] = pr; ai[k] = pi; }
        }
    } else if (BC >= 3) {
        constexpr int M = (BT < 3) ? (1 << BT) : 1;
        bool ctrl = ((lane >> (BC - 3)) & 1) != 0;
#pragma unroll
        for (int k = 0; k < 8; k++) if (!(k & M)) {
            const int k1 = k | M;
            float t0r = ctrl ? ar[k1] : ar[k];
            float t1r = ctrl ? ar[k]  : ar[k1];
            float t0i = ctrl ? ai[k1] : ai[k];
            float t1i = ctrl ? ai[k]  : ai[k1];
            ar[k] = t0r; ar[k1] = t1r; ai[k] = t0i; ai[k1] = t1i;
        }
    } else if (BT >= 3) {
        constexpr int delta = (BT >= 3) ? (1 << (BT - 3)) : 1;
        constexpr int MC = (BC < 3) ? (1 << BC) : 1;
#pragma unroll
        for (int k = 0; k < 8; k++) if (k & MC) {
            ar[k] = __shfl_xor_sync(FULLM, ar[k], delta);
            ai[k] = __shfl_xor_sync(FULLM, ai[k], delta);
        }
    } else {
        constexpr int MC = (BC < 3) ? (1 << BC) : 1;
        constexpr int M  = (BT < 3) ? (1 << BT) : 1;
#pragma unroll
        for (int k = 0; k < 8; k++) if ((k & MC) && !(k & M)) {
            const int k1 = k | M;
            float t = ar[k]; ar[k] = ar[k1]; ar[k1] = t;
            t = ai[k]; ai[k] = ai[k1]; ai[k1] = t;
        }
    }
}

template<int I>
__device__ __forceinline__ void apply_ops(float* ar, float* ai,
                                          const float* Pc, const float* Ps, int lane) {
    if constexpr (I < NOPS) {
        constexpr int ty = COPS.type[I];
        if constexpr (ty == 3) {
            cnot_t<7 - COPS.pa[I], 7 - COPS.pb[I]>(ar, ai, lane);
        } else {
            constexpr int bb = 7 - COPS.pa[I];
            const float c = Pc[I], s = Ps[I];
            if constexpr (ty == 2)      rz_t<bb>(ar, ai, c, s, lane);
            else if constexpr (bb >= 3) rot_lane_t<bb, ty == 0>(ar, ai, c, s, lane);
            else                        rot_intra_tt<(1 << bb), ty == 0>(ar, ai, c, s);
        }
        apply_ops<I + 1>(ar, ai, Pc, Ps, lane);
    }
}

template<int W>
__device__ __forceinline__ void apply_phiq(float* ar, float* ai, int lane) {
    if constexpr (W < 8) {
        float c = g_phiq_c[W];
        float s = g_phiq_s[W];
        constexpr int BB = 7 - W;
        if constexpr (BB >= 3) rot_lane_t<BB, true>(ar, ai, c, s, lane);
        else                   rot_intra_tt<(1 << BB), true>(ar, ai, c, s);
        apply_phiq<W + 1>(ar, ai, lane);
    }
}

// ============================================================================
// FUSED kernel.
//   blocks [0,128): recurrence, warp 0 only. One release-RED per step (lane 0),
//                   counters padded to one L2 line per step.
//   blocks [128, 128+2048): head. All 8 warps of a CTA share one bp; ONLY
//                   thread 0 polls, then __syncthreads.
// ============================================================================
__global__ void __launch_bounds__(256) k_fused(const float* __restrict__ Win,
                                               const float* __restrict__ Wout,
                                               const float* __restrict__ b_out,
                                               const float* __restrict__ Whead,
                                               const float* __restrict__ b_head,
                                               float* __restrict__ out,
                                               Angles A) {
    int bid = blockIdx.x;
    int tid = threadIdx.x;
    int lane = tid & 31;
    int wid  = tid >> 5;

    if (bid < RECUR_BLKS) {
        // ---------------- recurrence role: warp 0 only ----------------
        if (wid != 0) return;
        __shared__ __align__(16) float sp[32];
        __shared__ __align__(16) float sact[32];
        __shared__ __align__(16) float sh[8];

        int b = bid;
        int g = lane >> 3;
        int q = lane & 7;
        int base = lane & 24;

        float Wh[8];
#pragma unroll
        for (int j = 0; j < 8; j++) Wh[j] = Win[lane * 72 + 64 + j];
        float Wo[8];
#pragma unroll
        for (int j = 0; j < 8; j++) Wo[j] = Wout[g * 64 + q * 8 + j];
        float bo = b_out[lane];

        float aAB = (g == 2) ? 1.f : 0.5f;
        float aC  = (g == 2) ? 0.f : 0.5f;

        float h[8];
#pragma unroll
        for (int j = 0; j < 8; j++) h[j] = 0.f;
        float cst = 0.f;

        const int BSTR = BATCH * 32;
        const float* Zp = g_Zx + b * 32 + lane;
        float zA = Zp[0];
        float zB = Zp[BSTR];

#pragma unroll 2
        for (int s = 0; s < S_LEN; s++) {
            float zC = (s + 2 < S_LEN) ? Zp[(s + 2) * BSTR] : 0.f;

            float za = zA, zb = 0.f;
#pragma unroll
            for (int j = 0; j < 8; j += 2) {
                za = fmaf(Wh[j],     h[j],     za);
                zb = fmaf(Wh[j + 1], h[j + 1], zb);
            }
            float p = __cosf(za + zb);

            sp[lane] = p;
            __syncwarp();
            float4 pa = *reinterpret_cast<const float4*>(sp + base);
            float4 pb = *reinterpret_cast<const float4*>(sp + base + 4);

            float t01 = pa.x * pa.y, t23 = pa.z * pa.w;
            float t45 = pb.x * pb.y, t67 = pb.z * pb.w;
            float q03 = t01 * t23;
            float P0 = pa.x;
            float P1 = t01;
            float P2 = t01 * pa.z;
            float P3 = q03;
            float P4 = q03 * pb.x;
            float P5 = q03 * t45;
            float P6 = P5 * pb.z;
            float P7 = q03 * (t45 * t67);

            float prA = fmaf(Wo[0], P0, bo);
            float prB = Wo[1] * P1;
            prA = fmaf(Wo[2], P2, prA);
            prB = fmaf(Wo[3], P3, prB);
            prA = fmaf(Wo[4], P4, prA);
            prB = fmaf(Wo[5], P5, prB);
            prA = fmaf(Wo[6], P6, prA);
            prB = fmaf(Wo[7], P7, prB);
            float pre = prA + prB;

            float act = fmaf(aAB, fast_tanh(aAB * pre), aC);

            sact[lane] = act;
            __syncwarp();
            float fv = sact[q];
            float iv = sact[8 + q];
            float gv = sact[16 + q];
            float ov = sact[24 + q];

            cst = fmaf(fv, cst, iv * gv);
            float hval = ov * fast_tanh(cst);

            if (lane < 8) {
                sh[lane] = hval;
                g_hs[(s * BATCH + b) * HDIM + lane] = hval;
            }
            __syncwarp();   // orders all 8 lanes' g_hs stores before lane 0's release
            if (lane == 0) red_release_add(&g_cnt[s * CNT_STRIDE], 1u);
            float4 h0 = *reinterpret_cast<const float4*>(sh);
            float4 h1 = *reinterpret_cast<const float4*>(sh + 4);
            h[0] = h0.x; h[1] = h0.y; h[2] = h0.z; h[3] = h0.w;
            h[4] = h1.x; h[5] = h1.y; h[6] = h1.z; h[7] = h1.w;

            zA = zB; zB = zC;
        }
        return;
    }

    // ---------------- head role ----------------
    // CTA covers 8 rows sharing one bp: h = bid-128; bp = h & 127; sgrp = h >> 7.
    int hh  = bid - RECUR_BLKS;
    int bp  = hh & 127;             // recurrence step needed
    int sgrp = hh >> 7;             // 0..15
    int sp_ = sgrp * 8 + wid;       // s' for this warp
    int r   = sp_ * 128 + bp;       // output row
    int hoff = ((bp << 7) + sp_) * HDIM;

    // single poller per CTA on a private padded line
    if (tid == 0) {
        while (ld_acquire(&g_cnt[bp * CNT_STRIDE]) < CNT_TARGET) __nanosleep(128);
    }
    __syncthreads();

    // ---- encode: product state from RY angles ----
    float ce = 1.f, se = 0.f;
    if (lane < 8) {
        float th = 0.5f * g_hs[hoff + lane];
        __sincosf(th, &se, &ce);
    }
    float Fl = 1.f;
#pragma unroll
    for (int w = 0; w < 5; w++) {
        float cw = __shfl_sync(FULLM, ce, w);
        float sw = __shfl_sync(FULLM, se, w);
        Fl *= ((lane >> (4 - w)) & 1) ? sw : cw;
    }
    float c5 = __shfl_sync(FULLM, ce, 5), s5v = __shfl_sync(FULLM, se, 5);
    float c6 = __shfl_sync(FULLM, ce, 6), s6v = __shfl_sync(FULLM, se, 6);
    float c7 = __shfl_sync(FULLM, ce, 7), s7v = __shfl_sync(FULLM, se, 7);
    float ar[8], ai[8];
#pragma unroll
    for (int k = 0; k < 8; k++) {
        float f = ((k & 4) ? s5v : c5) * ((k & 2) ? s6v : c6) * ((k & 1) ? s7v : c7);
        ar[k] = Fl * f; ai[k] = 0.f;
    }

    apply_ops<0>(ar, ai, A.c, A.s, lane);
    apply_phiq<0>(ar, ai, lane);

    // ---- measure <Z_w> ----
    float p[8];
#pragma unroll
    for (int k = 0; k < 8; k++) p[k] = fmaf(ar[k], ar[k], ai[k] * ai[k]);
    float tot = 0.f, sA = 0.f, sB = 0.f, sC = 0.f;
#pragma unroll
    for (int k = 0; k < 8; k++) {
        tot += p[k];
        sA += (k & 4) ? -p[k] : p[k];
        sB += (k & 2) ? -p[k] : p[k];
        sC += (k & 1) ? -p[k] : p[k];
    }
    float x = tot;
#pragma unroll
    for (int d = 16; d >= 1; d >>= 1) {
        float o = __shfl_xor_sync(FULLM, x, d);
        x = (lane & d) ? (o - x) : (x + o);
    }
    float z[8];
    z[0] = __shfl_sync(FULLM, x, 16);
    z[1] = __shfl_sync(FULLM, x, 8);
    z[2] = __shfl_sync(FULLM, x, 4);
    z[3] = __shfl_sync(FULLM, x, 2);
    z[4] = __shfl_sync(FULLM, x, 1);
#pragma unroll
    for (int d = 16; d >= 1; d >>= 1) {
        sA += __shfl_xor_sync(FULLM, sA, d);
        sB += __shfl_xor_sync(FULLM, sB, d);
        sC += __shfl_xor_sync(FULLM, sC, d);
    }
    z[5] = sA; z[6] = sB; z[7] = sC;

    // ---- logits + log_softmax over T=12 ----
    float lg = 0.f;
    if (lane < TDIM) {
        lg = b_head[lane];
#pragma unroll
        for (int k = 0; k < 8; k++) lg = fmaf(z[k], Whead[lane * 8 + k], lg);
    }
    float mv = (lane < TDIM) ? lg : -3.0e38f;
#pragma unroll
    for (int d = 16; d >= 1; d >>= 1) mv = fmaxf(mv, __shfl_xor_sync(FULLM, mv, d));
    float ev = (lane < TDIM) ? __expf(lg - mv) : 0.f;
#pragma unroll
    for (int d = 16; d >= 1; d >>= 1) ev += __shfl_xor_sync(FULLM, ev, d);
    if (lane < TDIM) out[r * TDIM + lane] = lg - mv - __logf(ev);
}

// ============================================================================
// Launch
// ============================================================================
extern "C" void kernel_launch(void* const* d_in, const int* in_sizes, int n_in,
                              void* d_out, int out_size) {
    (void)in_sizes; (void)n_in; (void)out_size;
    const float* emb    = (const float*)d_in[0];
    const float* Win    = (const float*)d_in[1];
    const float* b_in   = (const float*)d_in[2];
    const float* phi    = (const float*)d_in[3];
    const float* Wout   = (const float*)d_in[4];
    const float* b_out  = (const float*)d_in[5];
    const float* phiq   = (const float*)d_in[6];
    const float* Whead  = (const float*)d_in[7];
    const float* b_head = (const float*)d_in[8];
    const int*   sent32 = (const int*)d_in[9];
    float* out = (float*)d_out;

    Angles A;
    build_angles(A);   // deterministic; recomputed every call (cheap)

    k_detect<<<1, 1024>>>((const int4*)sent32, phiq);
    k_project<<<NROWS / PROJ_ROWS, 256>>>(emb, Win, b_in, phi, sent32);
    k_fused<<<RECUR_BLKS + NROWS / 8, 256>>>(Win, Wout, b_out, Whead, b_head, out, A);
}